// round 7
// baseline (speedup 1.0000x reference)
#include <cuda_runtime.h>
#include <cuda_bf16.h>
#include <cstdint>

#define B_    16
#define CIN   32
#define COUT  32
#define H_    256
#define W_    256
#define EMB2  512

__device__ float g_wadapt[B_ * CIN];
__device__ float g_bfinal[B_ * COUT];
// Pre-built B fragments: [b][set(144)][lane(32)] as (reg0,reg1).
// set = ((tap*2+ks)*2 + hl)*4 + nt
__device__ uint2 g_bfrag[B_ * 144 * 32];

// ---------------------------------------------------------------------------
// PTX helpers (generic, sm_80+)
// ---------------------------------------------------------------------------
__device__ __forceinline__ uint32_t smem_u32(const void* p) {
    uint32_t a;
    asm("{ .reg .u64 t; cvta.to.shared.u64 t, %1; cvt.u32.u64 %0, t; }"
        : "=r"(a) : "l"(p));
    return a;
}
__device__ __forceinline__ void ldsm4(uint32_t* r, uint32_t a) {
    asm volatile("ldmatrix.sync.aligned.m8n8.x4.shared.b16 {%0,%1,%2,%3}, [%4];"
                 : "=r"(r[0]), "=r"(r[1]), "=r"(r[2]), "=r"(r[3]) : "r"(a));
}
__device__ __forceinline__ void ldsm2(uint32_t* r, uint32_t a) {
    asm volatile("ldmatrix.sync.aligned.m8n8.x2.shared.b16 {%0,%1}, [%2];"
                 : "=r"(r[0]), "=r"(r[1]) : "r"(a));
}
__device__ __forceinline__ void mma16816(float* d, const uint32_t* a,
                                         uint32_t b0, uint32_t b1) {
    asm volatile(
        "mma.sync.aligned.m16n8k16.row.col.f32.bf16.bf16.f32 "
        "{%0,%1,%2,%3}, {%4,%5,%6,%7}, {%8,%9}, {%0,%1,%2,%3};"
        : "+f"(d[0]), "+f"(d[1]), "+f"(d[2]), "+f"(d[3])
        : "r"(a[0]), "r"(a[1]), "r"(a[2]), "r"(a[3]), "r"(b0), "r"(b1));
}

// ---------------------------------------------------------------------------
// Kernel A: adapt GEMVs (one warp per dot; 1024 dots)
// ---------------------------------------------------------------------------
__global__ void adapt_kernel(const float* __restrict__ cond,
                             const float* __restrict__ lpe,
                             const float* __restrict__ wa_w,
                             const float* __restrict__ wa_b,
                             const float* __restrict__ ba_w,
                             const float* __restrict__ ba_b,
                             const float* __restrict__ bias) {
    int gw   = blockIdx.x * (blockDim.x >> 5) + (threadIdx.x >> 5);
    int lane = threadIdx.x & 31;
    if (gw >= 2 * B_ * CIN) return;
    int isB = (gw >= B_ * CIN);
    int idx = isB ? gw - B_ * CIN : gw;
    int b = idx >> 5, c = idx & 31;

    const float4* w4 = (const float4*)((isB ? ba_w : wa_w) + c * EMB2);
    const float4* c4 = (const float4*)(cond + b * 256);
    const float4* l4 = (const float4*)(lpe  + b * 256);

    float s = 0.f;
#pragma unroll
    for (int k = 0; k < 4; k++) {
        int j = lane + 32 * k;
        float4 iv = (j < 64) ? c4[j] : l4[j - 64];
        float4 wv = w4[j];
        s += iv.x * wv.x + iv.y * wv.y + iv.z * wv.z + iv.w * wv.w;
    }
#pragma unroll
    for (int off = 16; off; off >>= 1) s += __shfl_xor_sync(0xffffffffu, s, off);

    if (lane == 0) {
        if (isB) g_bfinal[idx] = bias[c] * (s + ba_b[c]);
        else     g_wadapt[idx] = s + wa_b[c];
    }
}

// ---------------------------------------------------------------------------
// Kernel A2: per-batch B-fragment prep (one CTA per batch).
// ---------------------------------------------------------------------------
#define BROWS  288
#define BBYTES (BROWS * 128)

__global__ void __launch_bounds__(512)
bfrag_prep(const float* __restrict__ weights) {
    __shared__ char smB[BBYTES];
    const int tid  = threadIdx.x;
    const int warp = tid >> 5;
    const int lane = tid & 31;
    const int b    = blockIdx.x;

    for (int e = tid; e < CIN * COUT * 9; e += 512) {
        int ci  = e / 288;
        int rem = e - ci * 288;
        int o   = rem / 9;
        int kl  = rem - o * 9;
        float v = weights[e] * g_wadapt[b * CIN + ci];
        __nv_bfloat16 h = __float2bfloat16(v);
        __nv_bfloat16 l = __float2bfloat16(v - __bfloat162float(h));
        int r  = kl * 32 + o;
        int ch = (ci >> 3) ^ (r & 7);
        int cl = (4 + (ci >> 3)) ^ (r & 7);
        int wb = (ci & 7) * 2;
        *(__nv_bfloat16*)(smB + r * 128 + ch * 16 + wb) = h;
        *(__nv_bfloat16*)(smB + r * 128 + cl * 16 + wb) = l;
    }
    __syncthreads();

    const uint32_t sbB = smem_u32(smB);
    for (int s = warp; s < 144; s += 16) {
        int tap = s >> 4, ks = (s >> 3) & 1, hl = (s >> 2) & 1, nt = s & 3;
        int r  = tap * 32 + nt * 8 + (lane & 7);
        int c0 = hl * 4 + ks * 2 + ((lane >> 3) & 1);
        uint32_t f[2];
        ldsm2(f, sbB + r * 128 + (uint32_t)((c0 ^ (r & 7)) << 4));
        g_bfrag[((size_t)b * 144 + s) * 32 + lane] = make_uint2(f[0], f[1]);
    }
}

// ---------------------------------------------------------------------------
// Kernel B: conv mainloop. CTA = batch b, 4 output rows x 64 cols, all 32
// Cout; 256 thr = 8 warps; warp owns 32 pixels (2 m-tiles of 16). 2 CTAs/SM.
// A smem: 396 pixel-rows (6 halo rows x 66 halo cols) x 128B
//   [32x bf16 hi | 32x bf16 lo], 16B chunks XOR-swizzled by (p&7).
// B: fragments cached in CTA smem (one L2 read), mainloop uses LDS.64.
// ---------------------------------------------------------------------------
#define APIX   396
#define ABYTES (APIX * 128)               // 50688
#define BF_BYTES (144 * 32 * 8)           // 36864
#define SMEM_TOTAL (ABYTES + BF_BYTES)    // 87552
#define NTHR 256

__global__ void __launch_bounds__(NTHR, 2)
conv_mma(const float* __restrict__ x,
         float* __restrict__ out) {
    extern __shared__ __align__(128) char smA[];
    uint2* smBf = (uint2*)(smA + ABYTES);
    __shared__ float bfc[COUT];

    const int tid  = threadIdx.x;
    const int warp = tid >> 5;
    const int lane = tid & 31;
    const int b    = blockIdx.z;
    const int gy0  = blockIdx.y * 4;
    const int gx0  = blockIdx.x * 64;

    if (tid < COUT) bfc[tid] = g_bfinal[b * COUT + tid];

    // ---- Stage B fragments into smem (single L2 read, 36.9 KB) ----
    {
        const uint2* src = g_bfrag + (size_t)b * 144 * 32;
        for (int i = tid; i < 144 * 32; i += NTHR) smBf[i] = src[i];
    }

    // ---- Stage A: x tile with halo, ci-pairs, hi/lo bf16 split, swizzled ----
    const float* xb = x + (size_t)b * CIN * H_ * W_;
    for (int e = tid; e < (CIN / 2) * APIX; e += NTHR) {
        int cp = e / APIX;             // ci pair index 0..15
        int p  = e - cp * APIX;
        int iy = p / 66;
        int ix = p - iy * 66;
        int gy = gy0 - 1 + iy;
        int gx = gx0 - 1 + ix;
        int ci0 = 2 * cp;
        float v0 = 0.f, v1 = 0.f;
        if ((unsigned)gy < (unsigned)H_ && (unsigned)gx < (unsigned)W_) {
            const float* px = xb + (size_t)ci0 * (H_ * W_) + gy * W_ + gx;
            v0 = px[0];
            v1 = px[H_ * W_];
        }
        __nv_bfloat16 h0 = __float2bfloat16(v0);
        __nv_bfloat16 l0 = __float2bfloat16(v0 - __bfloat162float(h0));
        __nv_bfloat16 h1 = __float2bfloat16(v1);
        __nv_bfloat16 l1 = __float2bfloat16(v1 - __bfloat162float(h1));
        int ch = (cp >> 2) ^ (p & 7);         // hi chunk (ci0>>3 == cp>>2)
        int cl = (4 + (cp >> 2)) ^ (p & 7);   // lo chunk
        int wb = (ci0 & 7) * 2;               // 0,4,8,12
        *(__nv_bfloat162*)(smA + p * 128 + ch * 16 + wb) =
            __nv_bfloat162{h0, h1};
        *(__nv_bfloat162*)(smA + p * 128 + cl * 16 + wb) =
            __nv_bfloat162{l0, l1};
    }
    __syncthreads();

    // ---- MMA mainloop: 2 m-tiles per warp share each B-fragment load ----
    const uint32_t sbA = smem_u32(smA);
    const int kh = lane >> 4;

    int p0[2];
#pragma unroll
    for (int mt = 0; mt < 2; mt++) {
        int m = warp * 32 + mt * 16 + (lane & 15);
        p0[mt] = (m >> 6) * 66 + (m & 63);
    }

    float acc[2][4][4];
#pragma unroll
    for (int mt = 0; mt < 2; mt++)
#pragma unroll
        for (int nt = 0; nt < 4; nt++)
#pragma unroll
            for (int j = 0; j < 4; j++) acc[mt][nt][j] = 0.f;

#pragma unroll
    for (int tap = 0; tap < 9; tap++) {
        const int pshift = (tap / 3) * 66 + (tap % 3);
#pragma unroll
        for (int ks = 0; ks < 2; ks++) {
            // B fragments for this (tap,ks): 8 x LDS.64, conflict-free
            uint2 bf[8];
            const int s0 = (tap * 2 + ks) * 8;
#pragma unroll
            for (int i = 0; i < 8; i++) bf[i] = smBf[(s0 + i) * 32 + lane];

#pragma unroll
            for (int mt = 0; mt < 2; mt++) {
                const int pa = p0[mt] + pshift;
                const uint32_t arow = sbA + pa * 128;
                const int     psw  = pa & 7;
                uint32_t ah[4], al[4];
                ldsm4(ah, arow + (uint32_t)(((ks * 2 + kh)     ^ psw) << 4));
                ldsm4(al, arow + (uint32_t)(((4 + ks * 2 + kh) ^ psw) << 4));
#pragma unroll
                for (int nt = 0; nt < 4; nt++) {
                    mma16816(acc[mt][nt], ah, bf[nt].x,     bf[nt].y);     // hh
                    mma16816(acc[mt][nt], al, bf[nt].x,     bf[nt].y);     // lh
                    mma16816(acc[mt][nt], ah, bf[4 + nt].x, bf[4 + nt].y); // hl
                }
            }
        }
    }

    // ---- Epilogue: bias add + stores ----
#pragma unroll
    for (int mt = 0; mt < 2; mt++) {
        const int row0 = warp * 32 + mt * 16 + (lane >> 2);
#pragma unroll
        for (int nt = 0; nt < 4; nt++) {
#pragma unroll
            for (int j = 0; j < 4; j++) {
                int o  = nt * 8 + (lane & 3) * 2 + (j & 1);
                int mm = row0 + (j >> 1) * 8;
                int gy = gy0 + (mm >> 6);
                int gx = gx0 + (mm & 63);
                out[(((size_t)b * COUT + o) * H_ + gy) * W_ + gx] =
                    acc[mt][nt][j] + bfc[o];
            }
        }
    }
}

// ---------------------------------------------------------------------------
extern "C" void kernel_launch(void* const* d_in, const int* in_sizes, int n_in,
                              void* d_out, int out_size) {
    const float* x    = (const float*)d_in[0];
    const float* cond = (const float*)d_in[1];
    const float* lpe  = (const float*)d_in[2];
    const float* w    = (const float*)d_in[3];
    const float* bias = (const float*)d_in[4];
    const float* wa_w = (const float*)d_in[5];
    const float* wa_b = (const float*)d_in[6];
    const float* ba_w = (const float*)d_in[7];
    const float* ba_b = (const float*)d_in[8];
    float* out = (float*)d_out;

    cudaFuncSetAttribute(conv_mma,
                         cudaFuncAttributeMaxDynamicSharedMemorySize, SMEM_TOTAL);

    adapt_kernel<<<128, 256>>>(cond, lpe, wa_w, wa_b, ba_w, ba_b, bias);
    bfrag_prep<<<B_, 512>>>(w);

    dim3 grid(W_ / 64, H_ / 4, B_);
    conv_mma<<<grid, NTHR, SMEM_TOTAL>>>(x, out);
}

// round 8
// speedup vs baseline: 1.2880x; 1.2880x over previous
#include <cuda_runtime.h>
#include <cuda_bf16.h>
#include <cstdint>

#define B_    16
#define CIN   32
#define COUT  32
#define H_    256
#define W_    256
#define HW    (H_ * W_)

__device__ float g_bfinal[B_ * COUT];
// B fragments: [b][g=tap*2+ks (18)][fp (4)][lane (32)] uint4 = frag pair
// (frag f = hl*4+nt; fp = f>>1, .xy = even f, .zw = odd f)
__device__ uint4 g_bfrag4[B_ * 18 * 4 * 32];

// ---------------------------------------------------------------------------
// PTX helpers (generic, sm_80+)
// ---------------------------------------------------------------------------
__device__ __forceinline__ uint32_t smem_u32(const void* p) {
    uint32_t a;
    asm("{ .reg .u64 t; cvta.to.shared.u64 t, %1; cvt.u32.u64 %0, t; }"
        : "=r"(a) : "l"(p));
    return a;
}
__device__ __forceinline__ void ldsm4(uint32_t* r, uint32_t a) {
    asm volatile("ldmatrix.sync.aligned.m8n8.x4.shared.b16 {%0,%1,%2,%3}, [%4];"
                 : "=r"(r[0]), "=r"(r[1]), "=r"(r[2]), "=r"(r[3]) : "r"(a));
}
__device__ __forceinline__ void ldsm2(uint32_t* r, uint32_t a) {
    asm volatile("ldmatrix.sync.aligned.m8n8.x2.shared.b16 {%0,%1}, [%2];"
                 : "=r"(r[0]), "=r"(r[1]) : "r"(a));
}
__device__ __forceinline__ void mma16816(float* d, const uint32_t* a,
                                         uint32_t b0, uint32_t b1) {
    asm volatile(
        "mma.sync.aligned.m16n8k16.row.col.f32.bf16.bf16.f32 "
        "{%0,%1,%2,%3}, {%4,%5,%6,%7}, {%8,%9}, {%0,%1,%2,%3};"
        : "+f"(d[0]), "+f"(d[1]), "+f"(d[2]), "+f"(d[3])
        : "r"(a[0]), "r"(a[1]), "r"(a[2]), "r"(a[3]), "r"(b0), "r"(b1));
}

// ---------------------------------------------------------------------------
// Prep kernel: one CTA per batch (512 thr). Computes the adapt GEMVs for its
// batch, builds the scaled hi/lo-split swizzled B tile in smem, then emits
// ldsm2-exact per-lane fragments to g_bfrag4 in the LDG.128-friendly layout.
// ---------------------------------------------------------------------------
#define BROWS  288
#define BBYTES (BROWS * 128)

__global__ void __launch_bounds__(512)
prep_kernel(const float* __restrict__ cond,
            const float* __restrict__ lpe,
            const float* __restrict__ wa_w,
            const float* __restrict__ wa_b,
            const float* __restrict__ ba_w,
            const float* __restrict__ ba_b,
            const float* __restrict__ bias,
            const float* __restrict__ weights) {
    __shared__ float ivec[512];
    __shared__ float wad[CIN];
    __shared__ char  smB[BBYTES];

    const int tid  = threadIdx.x;
    const int warp = tid >> 5;
    const int lane = tid & 31;
    const int b    = blockIdx.x;

    ivec[tid] = (tid < 256) ? cond[b * 256 + tid] : lpe[b * 256 + tid - 256];
    __syncthreads();

    // 64 dot products (32 wadapt + 32 badapt), 4 per warp
    for (int d = warp; d < 64; d += 16) {
        int isB = d >= 32, c = d & 31;
        const float* wr = (isB ? ba_w : wa_w) + c * 512;
        float s = 0.f;
#pragma unroll
        for (int k = lane; k < 512; k += 32) s += ivec[k] * wr[k];
#pragma unroll
        for (int off = 16; off; off >>= 1) s += __shfl_xor_sync(0xffffffffu, s, off);
        if (lane == 0) {
            if (isB) g_bfinal[b * COUT + c] = bias[c] * (s + ba_b[c]);
            else     wad[c] = s + wa_b[c];
        }
    }
    __syncthreads();

    // Build scaled hi/lo split swizzled B
    for (int e = tid; e < CIN * COUT * 9; e += 512) {
        int ci  = e / 288;
        int rem = e - ci * 288;
        int o   = rem / 9;
        int kl  = rem - o * 9;
        float v = weights[e] * wad[ci];
        __nv_bfloat16 h = __float2bfloat16(v);
        __nv_bfloat16 l = __float2bfloat16(v - __bfloat162float(h));
        int r  = kl * 32 + o;
        int ch = (ci >> 3) ^ (r & 7);
        int cl = (4 + (ci >> 3)) ^ (r & 7);
        int wb = (ci & 7) * 2;
        *(__nv_bfloat16*)(smB + r * 128 + ch * 16 + wb) = h;
        *(__nv_bfloat16*)(smB + r * 128 + cl * 16 + wb) = l;
    }
    __syncthreads();

    // Emit fragments (ldsm2-exact) in paired layout
    const uint32_t sbB = smem_u32(smB);
    uint2* dst = (uint2*)g_bfrag4;
    for (int s = warp; s < 144; s += 16) {
        int tap = s >> 4, ks = (s >> 3) & 1, hl = (s >> 2) & 1, nt = s & 3;
        int r  = tap * 32 + nt * 8 + (lane & 7);
        int c0 = hl * 4 + ks * 2 + ((lane >> 3) & 1);
        uint32_t f[2];
        ldsm2(f, sbB + r * 128 + (uint32_t)((c0 ^ (r & 7)) << 4));
        int g    = tap * 2 + ks;
        int fidx = hl * 4 + nt;
        dst[((((size_t)b * 18 + g) * 4 + (fidx >> 1)) * 32 + lane) * 2 + (fidx & 1)] =
            make_uint2(f[0], f[1]);
    }
}

// ---------------------------------------------------------------------------
// Conv mainloop. CTA = batch b, 2 output rows x 64 cols, all 32 Cout;
// 256 thr = 8 warps; warp owns 16 output pixels; 3 CTAs/SM.
// A smem: 264 pixel-rows (4 halo rows x 66 halo cols) x 128B
//   [32x bf16 hi | 32x bf16 lo], 16B chunks XOR-swizzled by (p&7).
// B: 4 coalesced LDG.128 per (tap,ks) from g_bfrag4 (L1-resident).
// ---------------------------------------------------------------------------
#define APIX   264
#define ABYTES (APIX * 128)     // 33792
#define NTHR 256

__global__ void __launch_bounds__(NTHR, 3)
conv_mma(const float* __restrict__ x,
         float* __restrict__ out) {
    extern __shared__ __align__(128) char smA[];
    __shared__ float bfc[COUT];

    const int tid  = threadIdx.x;
    const int warp = tid >> 5;
    const int lane = tid & 31;
    const int b    = blockIdx.z;
    const int gy0  = blockIdx.y * 2;
    const int gx0  = blockIdx.x * 64;

    if (tid < COUT) bfc[tid] = g_bfinal[b * COUT + tid];

    // ---- Stage A: division-free, ci-pair loop, bf16x2 stores ----
    const float* xb = x + (size_t)b * CIN * HW;
    for (int p = tid; p < APIX; p += NTHR) {
        const int iy = p / 66;
        const int ix = p - iy * 66;
        const int gy = gy0 - 1 + iy;
        const int gx = gx0 - 1 + ix;
        const bool ok = (unsigned)gy < (unsigned)H_ && (unsigned)gx < (unsigned)W_;
        const float* px = xb + (size_t)(ok ? gy * W_ + gx : 0);
        char* arow = smA + p * 128;
        const int psw = p & 7;
#pragma unroll 4
        for (int cp = 0; cp < 16; cp++) {
            float v0 = 0.f, v1 = 0.f;
            if (ok) {
                v0 = px[(size_t)(2 * cp) * HW];
                v1 = px[(size_t)(2 * cp + 1) * HW];
            }
            __nv_bfloat16 h0 = __float2bfloat16(v0);
            __nv_bfloat16 l0 = __float2bfloat16(v0 - __bfloat162float(h0));
            __nv_bfloat16 h1 = __float2bfloat16(v1);
            __nv_bfloat16 l1 = __float2bfloat16(v1 - __bfloat162float(h1));
            const int ch = (cp >> 2) ^ psw;
            const int cl = (4 + (cp >> 2)) ^ psw;
            const int wb = ((2 * cp) & 7) * 2;
            *(__nv_bfloat162*)(arow + ch * 16 + wb) = __nv_bfloat162{h0, h1};
            *(__nv_bfloat162*)(arow + cl * 16 + wb) = __nv_bfloat162{l0, l1};
        }
    }
    __syncthreads();

    // ---- MMA mainloop ----
    const uint32_t sbA = smem_u32(smA);
    const int m  = warp * 16 + (lane & 15);
    const int p0 = (m >> 6) * 66 + (m & 63);
    const int kh = lane >> 4;
    const uint4* __restrict__ bfb = g_bfrag4 + (size_t)b * 18 * 4 * 32 + lane;

    float acc[4][4];
#pragma unroll
    for (int nt = 0; nt < 4; nt++)
#pragma unroll
        for (int j = 0; j < 4; j++) acc[nt][j] = 0.f;

#pragma unroll
    for (int tap = 0; tap < 9; tap++) {
        const int pa = p0 + (tap / 3) * 66 + (tap % 3);
        const uint32_t arow = sbA + pa * 128;
        const int     psw  = pa & 7;
#pragma unroll
        for (int ks = 0; ks < 2; ks++) {
            // B: 4 coalesced LDG.128 (frag pairs) for this (tap,ks)
            const uint4* bp = bfb + (size_t)(tap * 2 + ks) * 4 * 32;
            uint4 q0 = bp[0 * 32];
            uint4 q1 = bp[1 * 32];
            uint4 q2 = bp[2 * 32];
            uint4 q3 = bp[3 * 32];

            uint32_t ah[4], al[4];
            ldsm4(ah, arow + (uint32_t)(((ks * 2 + kh)     ^ psw) << 4));
            ldsm4(al, arow + (uint32_t)(((4 + ks * 2 + kh) ^ psw) << 4));

            // hh + lh with hi-B frags (q0,q1), hl with lo-B frags (q2,q3)
            mma16816(acc[0], ah, q0.x, q0.y);
            mma16816(acc[0], al, q0.x, q0.y);
            mma16816(acc[0], ah, q2.x, q2.y);
            mma16816(acc[1], ah, q0.z, q0.w);
            mma16816(acc[1], al, q0.z, q0.w);
            mma16816(acc[1], ah, q2.z, q2.w);
            mma16816(acc[2], ah, q1.x, q1.y);
            mma16816(acc[2], al, q1.x, q1.y);
            mma16816(acc[2], ah, q3.x, q3.y);
            mma16816(acc[3], ah, q1.z, q1.w);
            mma16816(acc[3], al, q1.z, q1.w);
            mma16816(acc[3], ah, q3.z, q3.w);
        }
    }

    // ---- Epilogue: bias add + stores ----
    const int row0 = warp * 16 + (lane >> 2);
#pragma unroll
    for (int nt = 0; nt < 4; nt++) {
#pragma unroll
        for (int j = 0; j < 4; j++) {
            int o  = nt * 8 + (lane & 3) * 2 + (j & 1);
            int mm = row0 + (j >> 1) * 8;
            int gy = gy0 + (mm >> 6);
            int gx = gx0 + (mm & 63);
            out[(((size_t)b * COUT + o) * H_ + gy) * W_ + gx] = acc[nt][j] + bfc[o];
        }
    }
}

// ---------------------------------------------------------------------------
extern "C" void kernel_launch(void* const* d_in, const int* in_sizes, int n_in,
                              void* d_out, int out_size) {
    const float* x    = (const float*)d_in[0];
    const float* cond = (const float*)d_in[1];
    const float* lpe  = (const float*)d_in[2];
    const float* w    = (const float*)d_in[3];
    const float* bias = (const float*)d_in[4];
    const float* wa_w = (const float*)d_in[5];
    const float* wa_b = (const float*)d_in[6];
    const float* ba_w = (const float*)d_in[7];
    const float* ba_b = (const float*)d_in[8];
    float* out = (float*)d_out;

    prep_kernel<<<B_, 512>>>(cond, lpe, wa_w, wa_b, ba_w, ba_b, bias, w);

    dim3 grid(W_ / 64, H_ / 2, B_);
    conv_mma<<<grid, NTHR, ABYTES>>>(x, out);
}

// round 9
// speedup vs baseline: 1.5791x; 1.2261x over previous
#include <cuda_runtime.h>
#include <cuda_bf16.h>
#include <cstdint>

#define B_    16
#define CIN   32
#define COUT  32
#define H_    256
#define W_    256
#define HW    (H_ * W_)

__device__ float g_bfinal[B_ * COUT];
// B fragments: [b][g=tap*2+ks (18)][fp (4)][lane (32)] uint4 = frag pair
// (frag f = hl*4+nt; fp = f>>1, .xy = even f, .zw = odd f)
__device__ uint4 g_bfrag4[B_ * 18 * 4 * 32];

// ---------------------------------------------------------------------------
// PTX helpers (generic, sm_80+)
// ---------------------------------------------------------------------------
__device__ __forceinline__ uint32_t smem_u32(const void* p) {
    uint32_t a;
    asm("{ .reg .u64 t; cvta.to.shared.u64 t, %1; cvt.u32.u64 %0, t; }"
        : "=r"(a) : "l"(p));
    return a;
}
__device__ __forceinline__ void ldsm4(uint32_t* r, uint32_t a) {
    asm volatile("ldmatrix.sync.aligned.m8n8.x4.shared.b16 {%0,%1,%2,%3}, [%4];"
                 : "=r"(r[0]), "=r"(r[1]), "=r"(r[2]), "=r"(r[3]) : "r"(a));
}
__device__ __forceinline__ void ldsm2(uint32_t* r, uint32_t a) {
    asm volatile("ldmatrix.sync.aligned.m8n8.x2.shared.b16 {%0,%1}, [%2];"
                 : "=r"(r[0]), "=r"(r[1]) : "r"(a));
}
__device__ __forceinline__ void mma16816(float* d, const uint32_t* a,
                                         uint32_t b0, uint32_t b1) {
    asm volatile(
        "mma.sync.aligned.m16n8k16.row.col.f32.bf16.bf16.f32 "
        "{%0,%1,%2,%3}, {%4,%5,%6,%7}, {%8,%9}, {%0,%1,%2,%3};"
        : "+f"(d[0]), "+f"(d[1]), "+f"(d[2]), "+f"(d[3])
        : "r"(a[0]), "r"(a[1]), "r"(a[2]), "r"(a[3]), "r"(b0), "r"(b1));
}

// ---------------------------------------------------------------------------
// Prep kernel: one CTA per batch (512 thr). Adapt GEMVs + scaled hi/lo-split
// swizzled B tile in smem + ldsm2-exact fragment emission to g_bfrag4.
// ---------------------------------------------------------------------------
#define BROWS  288
#define BBYTES (BROWS * 128)

__global__ void __launch_bounds__(512)
prep_kernel(const float* __restrict__ cond,
            const float* __restrict__ lpe,
            const float* __restrict__ wa_w,
            const float* __restrict__ wa_b,
            const float* __restrict__ ba_w,
            const float* __restrict__ ba_b,
            const float* __restrict__ bias,
            const float* __restrict__ weights) {
    __shared__ float ivec[512];
    __shared__ float wad[CIN];
    __shared__ char  smB[BBYTES];

    const int tid  = threadIdx.x;
    const int warp = tid >> 5;
    const int lane = tid & 31;
    const int b    = blockIdx.x;

    ivec[tid] = (tid < 256) ? cond[b * 256 + tid] : lpe[b * 256 + tid - 256];
    __syncthreads();

    for (int d = warp; d < 64; d += 16) {
        int isB = d >= 32, c = d & 31;
        const float* wr = (isB ? ba_w : wa_w) + c * 512;
        float s = 0.f;
#pragma unroll
        for (int k = lane; k < 512; k += 32) s += ivec[k] * wr[k];
#pragma unroll
        for (int off = 16; off; off >>= 1) s += __shfl_xor_sync(0xffffffffu, s, off);
        if (lane == 0) {
            if (isB) g_bfinal[b * COUT + c] = bias[c] * (s + ba_b[c]);
            else     wad[c] = s + wa_b[c];
        }
    }
    __syncthreads();

    for (int e = tid; e < CIN * COUT * 9; e += 512) {
        int ci  = e / 288;
        int rem = e - ci * 288;
        int o   = rem / 9;
        int kl  = rem - o * 9;
        float v = weights[e] * wad[ci];
        __nv_bfloat16 h = __float2bfloat16(v);
        __nv_bfloat16 l = __float2bfloat16(v - __bfloat162float(h));
        int r  = kl * 32 + o;
        int ch = (ci >> 3) ^ (r & 7);
        int cl = (4 + (ci >> 3)) ^ (r & 7);
        int wb = (ci & 7) * 2;
        *(__nv_bfloat16*)(smB + r * 128 + ch * 16 + wb) = h;
        *(__nv_bfloat16*)(smB + r * 128 + cl * 16 + wb) = l;
    }
    __syncthreads();

    const uint32_t sbB = smem_u32(smB);
    uint2* dst = (uint2*)g_bfrag4;
    for (int s = warp; s < 144; s += 16) {
        int tap = s >> 4, ks = (s >> 3) & 1, hl = (s >> 2) & 1, nt = s & 3;
        int r  = tap * 32 + nt * 8 + (lane & 7);
        int c0 = hl * 4 + ks * 2 + ((lane >> 3) & 1);
        uint32_t f[2];
        ldsm2(f, sbB + r * 128 + (uint32_t)((c0 ^ (r & 7)) << 4));
        int g    = tap * 2 + ks;
        int fidx = hl * 4 + nt;
        dst[((((size_t)b * 18 + g) * 4 + (fidx >> 1)) * 32 + lane) * 2 + (fidx & 1)] =
            make_uint2(f[0], f[1]);
    }
}

// ---------------------------------------------------------------------------
// Conv mainloop. CTA = batch b, 4 output rows x 64 cols, all 32 Cout;
// 256 thr = 8 warps; warp owns 32 pixels = 2 m-tiles sharing each B load;
// 3 CTAs/SM.
// A smem: 396 pixel-rows (6 halo rows x 66 halo cols) x 128B
//   [32x bf16 hi | 32x bf16 lo], 16B chunks XOR-swizzled by (p&7).
// B: 4 coalesced LDG.128 per (tap,ks) from g_bfrag4 (L1-resident),
//    amortized over 24 MMAs.
// ---------------------------------------------------------------------------
#define APIX   396
#define ABYTES (APIX * 128)     // 50688
#define NTHR 256

__global__ void __launch_bounds__(NTHR, 3)
conv_mma(const float* __restrict__ x,
         float* __restrict__ out) {
    extern __shared__ __align__(128) char smA[];
    __shared__ float bfc[COUT];

    const int tid  = threadIdx.x;
    const int warp = tid >> 5;
    const int lane = tid & 31;
    const int b    = blockIdx.z;
    const int gy0  = blockIdx.y * 4;
    const int gx0  = blockIdx.x * 64;

    if (tid < COUT) bfc[tid] = g_bfinal[b * COUT + tid];

    // ---- Stage A: division-free, ci-pair loop, bf16x2 stores ----
    const float* xb = x + (size_t)b * CIN * HW;
    for (int p = tid; p < APIX; p += NTHR) {
        const int iy = p / 66;
        const int ix = p - iy * 66;
        const int gy = gy0 - 1 + iy;
        const int gx = gx0 - 1 + ix;
        const bool ok = (unsigned)gy < (unsigned)H_ && (unsigned)gx < (unsigned)W_;
        const float* px = xb + (size_t)(ok ? gy * W_ + gx : 0);
        char* arow = smA + p * 128;
        const int psw = p & 7;
#pragma unroll 4
        for (int cp = 0; cp < 16; cp++) {
            float v0 = 0.f, v1 = 0.f;
            if (ok) {
                v0 = px[(size_t)(2 * cp) * HW];
                v1 = px[(size_t)(2 * cp + 1) * HW];
            }
            __nv_bfloat16 h0 = __float2bfloat16(v0);
            __nv_bfloat16 l0 = __float2bfloat16(v0 - __bfloat162float(h0));
            __nv_bfloat16 h1 = __float2bfloat16(v1);
            __nv_bfloat16 l1 = __float2bfloat16(v1 - __bfloat162float(h1));
            const int ch = (cp >> 2) ^ psw;
            const int cl = (4 + (cp >> 2)) ^ psw;
            const int wb = ((2 * cp) & 7) * 2;
            *(__nv_bfloat162*)(arow + ch * 16 + wb) = __nv_bfloat162{h0, h1};
            *(__nv_bfloat162*)(arow + cl * 16 + wb) = __nv_bfloat162{l0, l1};
        }
    }
    __syncthreads();

    // ---- MMA mainloop: 2 m-tiles share every B-fragment load ----
    const uint32_t sbA = smem_u32(smA);
    const int kh = lane >> 4;
    const uint4* __restrict__ bfb = g_bfrag4 + (size_t)b * 18 * 4 * 32 + lane;

    int p0[2];
#pragma unroll
    for (int mt = 0; mt < 2; mt++) {
        int m = warp * 32 + mt * 16 + (lane & 15);
        p0[mt] = (m >> 6) * 66 + (m & 63);
    }

    float acc[2][4][4];
#pragma unroll
    for (int mt = 0; mt < 2; mt++)
#pragma unroll
        for (int nt = 0; nt < 4; nt++)
#pragma unroll
            for (int j = 0; j < 4; j++) acc[mt][nt][j] = 0.f;

#pragma unroll
    for (int tap = 0; tap < 9; tap++) {
        const int pshift = (tap / 3) * 66 + (tap % 3);
#pragma unroll
        for (int ks = 0; ks < 2; ks++) {
            const uint4* bp = bfb + (size_t)(tap * 2 + ks) * 4 * 32;
            uint4 q0 = bp[0 * 32];
            uint4 q1 = bp[1 * 32];
            uint4 q2 = bp[2 * 32];
            uint4 q3 = bp[3 * 32];

#pragma unroll
            for (int mt = 0; mt < 2; mt++) {
                const int pa = p0[mt] + pshift;
                const uint32_t arow = sbA + pa * 128;
                const int     psw  = pa & 7;
                uint32_t ah[4], al[4];
                ldsm4(ah, arow + (uint32_t)(((ks * 2 + kh)     ^ psw) << 4));
                ldsm4(al, arow + (uint32_t)(((4 + ks * 2 + kh) ^ psw) << 4));

                float* a0 = acc[mt][0];
                float* a1 = acc[mt][1];
                float* a2 = acc[mt][2];
                float* a3 = acc[mt][3];
                mma16816(a0, ah, q0.x, q0.y);
                mma16816(a0, al, q0.x, q0.y);
                mma16816(a0, ah, q2.x, q2.y);
                mma16816(a1, ah, q0.z, q0.w);
                mma16816(a1, al, q0.z, q0.w);
                mma16816(a1, ah, q2.z, q2.w);
                mma16816(a2, ah, q1.x, q1.y);
                mma16816(a2, al, q1.x, q1.y);
                mma16816(a2, ah, q3.x, q3.y);
                mma16816(a3, ah, q1.z, q1.w);
                mma16816(a3, al, q1.z, q1.w);
                mma16816(a3, ah, q3.z, q3.w);
            }
        }
    }

    // ---- Epilogue: bias add + stores ----
#pragma unroll
    for (int mt = 0; mt < 2; mt++) {
        const int row0 = warp * 32 + mt * 16 + (lane >> 2);
#pragma unroll
        for (int nt = 0; nt < 4; nt++) {
#pragma unroll
            for (int j = 0; j < 4; j++) {
                int o  = nt * 8 + (lane & 3) * 2 + (j & 1);
                int mm = row0 + (j >> 1) * 8;
                int gy = gy0 + (mm >> 6);
                int gx = gx0 + (mm & 63);
                out[(((size_t)b * COUT + o) * H_ + gy) * W_ + gx] =
                    acc[mt][nt][j] + bfc[o];
            }
        }
    }
}

// ---------------------------------------------------------------------------
extern "C" void kernel_launch(void* const* d_in, const int* in_sizes, int n_in,
                              void* d_out, int out_size) {
    const float* x    = (const float*)d_in[0];
    const float* cond = (const float*)d_in[1];
    const float* lpe  = (const float*)d_in[2];
    const float* w    = (const float*)d_in[3];
    const float* bias = (const float*)d_in[4];
    const float* wa_w = (const float*)d_in[5];
    const float* wa_b = (const float*)d_in[6];
    const float* ba_w = (const float*)d_in[7];
    const float* ba_b = (const float*)d_in[8];
    float* out = (float*)d_out;

    cudaFuncSetAttribute(conv_mma,
                         cudaFuncAttributeMaxDynamicSharedMemorySize, ABYTES);

    prep_kernel<<<B_, 512>>>(cond, lpe, wa_w, wa_b, ba_w, ba_b, bias, w);

    dim3 grid(W_ / 64, H_ / 4, B_);
    conv_mma<<<grid, NTHR, ABYTES>>>(x, out);
}

// round 10
// speedup vs baseline: 1.6400x; 1.0386x over previous
#include <cuda_runtime.h>
#include <cuda_bf16.h>
#include <cstdint>

#define B_    16
#define CIN   32
#define COUT  32
#define H_    256
#define W_    256
#define HW    (H_ * W_)

__device__ float g_bfinal[B_ * COUT];
// B fragments: [b][g=tap*2+ks (18)][fp (4)][lane (32)] uint4 = frag pair
__device__ uint4 g_bfrag4[B_ * 18 * 4 * 32];

// ---------------------------------------------------------------------------
// PTX helpers (generic, sm_80+)
// ---------------------------------------------------------------------------
__device__ __forceinline__ uint32_t smem_u32(const void* p) {
    uint32_t a;
    asm("{ .reg .u64 t; cvta.to.shared.u64 t, %1; cvt.u32.u64 %0, t; }"
        : "=r"(a) : "l"(p));
    return a;
}
__device__ __forceinline__ void ldsm4(uint32_t* r, uint32_t a) {
    asm volatile("ldmatrix.sync.aligned.m8n8.x4.shared.b16 {%0,%1,%2,%3}, [%4];"
                 : "=r"(r[0]), "=r"(r[1]), "=r"(r[2]), "=r"(r[3]) : "r"(a));
}
__device__ __forceinline__ void ldsm2(uint32_t* r, uint32_t a) {
    asm volatile("ldmatrix.sync.aligned.m8n8.x2.shared.b16 {%0,%1}, [%2];"
                 : "=r"(r[0]), "=r"(r[1]) : "r"(a));
}
__device__ __forceinline__ void mma16816(float* d, const uint32_t* a,
                                         uint32_t b0, uint32_t b1) {
    asm volatile(
        "mma.sync.aligned.m16n8k16.row.col.f32.bf16.bf16.f32 "
        "{%0,%1,%2,%3}, {%4,%5,%6,%7}, {%8,%9}, {%0,%1,%2,%3};"
        : "+f"(d[0]), "+f"(d[1]), "+f"(d[2]), "+f"(d[3])
        : "r"(a[0]), "r"(a[1]), "r"(a[2]), "r"(a[3]), "r"(b0), "r"(b1));
}
__device__ __forceinline__ uint32_t pack_bf2(__nv_bfloat16 a, __nv_bfloat16 b) {
    return (uint32_t)__bfloat16_as_ushort(a) |
           ((uint32_t)__bfloat16_as_ushort(b) << 16);
}

// ---------------------------------------------------------------------------
// Prep kernel: grid (9 taps, 16 batches), 128 thr. Each CTA computes the
// wadapt dots (redundantly, cheap), builds its 32-row B slice (scaled,
// hi/lo split, swizzled) and emits ldsm2-exact fragments. Tap-0 CTAs also
// compute bfinal.
// ---------------------------------------------------------------------------
__global__ void __launch_bounds__(128)
prep_kernel(const float* __restrict__ cond,
            const float* __restrict__ lpe,
            const float* __restrict__ wa_w,
            const float* __restrict__ wa_b,
            const float* __restrict__ ba_w,
            const float* __restrict__ ba_b,
            const float* __restrict__ bias,
            const float* __restrict__ weights) {
    __shared__ float ivec[512];
    __shared__ float wad[CIN];
    __shared__ char  smB[32 * 128];

    const int tid  = threadIdx.x;
    const int warp = tid >> 5;
    const int lane = tid & 31;
    const int kl   = blockIdx.x;
    const int b    = blockIdx.y;

#pragma unroll
    for (int k = 0; k < 4; k++) {
        int idx = tid + 128 * k;
        ivec[idx] = (idx < 256) ? cond[b * 256 + idx] : lpe[b * 256 + idx - 256];
    }
    __syncthreads();

    // wadapt (all CTAs) + badapt/bfinal (tap-0 CTAs only)
    for (int d = warp; d < 32; d += 4) {
        const float* wr = wa_w + d * 512;
        float s = 0.f;
#pragma unroll
        for (int k = lane; k < 512; k += 32) s += ivec[k] * wr[k];
#pragma unroll
        for (int off = 16; off; off >>= 1) s += __shfl_xor_sync(0xffffffffu, s, off);
        if (lane == 0) wad[d] = s + wa_b[d];
    }
    if (kl == 0) {
        for (int d = warp; d < 32; d += 4) {
            const float* wr = ba_w + d * 512;
            float s = 0.f;
#pragma unroll
            for (int k = lane; k < 512; k += 32) s += ivec[k] * wr[k];
#pragma unroll
            for (int off = 16; off; off >>= 1) s += __shfl_xor_sync(0xffffffffu, s, off);
            if (lane == 0) g_bfinal[b * COUT + d] = bias[d] * (s + ba_b[d]);
        }
    }
    __syncthreads();

    // Build this tap's 32-row B slice (row o, local): scaled, hi/lo, swizzled
    for (int e = tid; e < 32 * 32; e += 128) {
        int ci = e >> 5;
        int o  = e & 31;
        float v = weights[(ci * 32 + o) * 9 + kl] * wad[ci];
        __nv_bfloat16 h = __float2bfloat16(v);
        __nv_bfloat16 l = __float2bfloat16(v - __bfloat162float(h));
        int ch = (ci >> 3) ^ (o & 7);
        int cl = (4 + (ci >> 3)) ^ (o & 7);
        int wb = (ci & 7) * 2;
        *(__nv_bfloat16*)(smB + o * 128 + ch * 16 + wb) = h;
        *(__nv_bfloat16*)(smB + o * 128 + cl * 16 + wb) = l;
    }
    __syncthreads();

    // Emit fragments: 16 (ks,hl,nt) combos for this tap
    const uint32_t sbB = smem_u32(smB);
    uint2* dst = (uint2*)g_bfrag4;
    for (int s = warp; s < 16; s += 4) {
        int ks = s >> 3, hl = (s >> 2) & 1, nt = s & 3;
        int r  = nt * 8 + (lane & 7);
        int c0 = hl * 4 + ks * 2 + ((lane >> 3) & 1);
        uint32_t f[2];
        ldsm2(f, sbB + r * 128 + (uint32_t)((c0 ^ (r & 7)) << 4));
        int g    = kl * 2 + ks;
        int fidx = hl * 4 + nt;
        dst[((((size_t)b * 18 + g) * 4 + (fidx >> 1)) * 32 + lane) * 2 + (fidx & 1)] =
            make_uint2(f[0], f[1]);
    }
}

// ---------------------------------------------------------------------------
// Conv mainloop. CTA = batch b, 4 output rows x 64 cols, all 32 Cout;
// 256 thr = 8 warps; warp owns 32 pixels = 2 m-tiles; 3 CTAs/SM.
// A smem: 396 pixel-rows x 128B [32 bf16 hi | 32 bf16 lo], 16B chunks
// XOR-swizzled by (p&7). Staging emits STS.128 per chunk (conflict-absorbed).
// Epilogue: warp-private smem transpose -> coalesced float4 STG.
// ---------------------------------------------------------------------------
#define APIX   396
#define ABYTES (APIX * 128)     // 50688
#define NTHR 256

__global__ void __launch_bounds__(NTHR, 3)
conv_mma(const float* __restrict__ x,
         float* __restrict__ out) {
    extern __shared__ __align__(128) char smA[];
    __shared__ float bfc[COUT];

    const int tid  = threadIdx.x;
    const int warp = tid >> 5;
    const int lane = tid & 31;
    const int b    = blockIdx.z;
    const int gy0  = blockIdx.y * 4;
    const int gx0  = blockIdx.x * 64;

    if (tid < COUT) bfc[tid] = g_bfinal[b * COUT + tid];

    // ---- Stage A: per pixel-row, 4 ci-octets -> 2x STS.128 each ----
    const float* xb = x + (size_t)b * CIN * HW;
    for (int p = tid; p < APIX; p += NTHR) {
        const int iy = p / 66;
        const int ix = p - iy * 66;
        const int gy = gy0 - 1 + iy;
        const int gx = gx0 - 1 + ix;
        const bool ok = (unsigned)gy < (unsigned)H_ && (unsigned)gx < (unsigned)W_;
        const float* px = xb + (size_t)(ok ? gy * W_ + gx : 0);
        char* arow = smA + p * 128;
        const int psw = p & 7;
#pragma unroll
        for (int c = 0; c < 4; c++) {
            float v[8];
#pragma unroll
            for (int j = 0; j < 8; j++)
                v[j] = ok ? px[(size_t)(8 * c + j) * HW] : 0.f;
            __nv_bfloat16 h[8];
            uint4 hv, lv;
#pragma unroll
            for (int j = 0; j < 8; j++) h[j] = __float2bfloat16(v[j]);
            hv.x = pack_bf2(h[0], h[1]);
            hv.y = pack_bf2(h[2], h[3]);
            hv.z = pack_bf2(h[4], h[5]);
            hv.w = pack_bf2(h[6], h[7]);
            __nv_bfloat16 l[8];
#pragma unroll
            for (int j = 0; j < 8; j++)
                l[j] = __float2bfloat16(v[j] - __bfloat162float(h[j]));
            lv.x = pack_bf2(l[0], l[1]);
            lv.y = pack_bf2(l[2], l[3]);
            lv.z = pack_bf2(l[4], l[5]);
            lv.w = pack_bf2(l[6], l[7]);
            *(uint4*)(arow + ((c ^ psw) << 4))       = hv;
            *(uint4*)(arow + (((c + 4) ^ psw) << 4)) = lv;
        }
    }
    __syncthreads();

    // ---- MMA mainloop: 2 m-tiles share every B-fragment load ----
    const uint32_t sbA = smem_u32(smA);
    const int kh = lane >> 4;
    const uint4* __restrict__ bfb = g_bfrag4 + (size_t)b * 18 * 4 * 32 + lane;

    int p0[2];
#pragma unroll
    for (int mt = 0; mt < 2; mt++) {
        int m = warp * 32 + mt * 16 + (lane & 15);
        p0[mt] = (m >> 6) * 66 + (m & 63);
    }

    float acc[2][4][4];
#pragma unroll
    for (int mt = 0; mt < 2; mt++)
#pragma unroll
        for (int nt = 0; nt < 4; nt++)
#pragma unroll
            for (int j = 0; j < 4; j++) acc[mt][nt][j] = 0.f;

#pragma unroll
    for (int tap = 0; tap < 9; tap++) {
        const int pshift = (tap / 3) * 66 + (tap % 3);
#pragma unroll
        for (int ks = 0; ks < 2; ks++) {
            const uint4* bp = bfb + (size_t)(tap * 2 + ks) * 4 * 32;
            uint4 q0 = bp[0 * 32];
            uint4 q1 = bp[1 * 32];
            uint4 q2 = bp[2 * 32];
            uint4 q3 = bp[3 * 32];

#pragma unroll
            for (int mt = 0; mt < 2; mt++) {
                const int pa = p0[mt] + pshift;
                const uint32_t arow = sbA + pa * 128;
                const int     psw  = pa & 7;
                uint32_t ah[4], al[4];
                ldsm4(ah, arow + (uint32_t)(((ks * 2 + kh)     ^ psw) << 4));
                ldsm4(al, arow + (uint32_t)(((4 + ks * 2 + kh) ^ psw) << 4));

                float* a0 = acc[mt][0];
                float* a1 = acc[mt][1];
                float* a2 = acc[mt][2];
                float* a3 = acc[mt][3];
                mma16816(a0, ah, q0.x, q0.y);
                mma16816(a0, al, q0.x, q0.y);
                mma16816(a0, ah, q2.x, q2.y);
                mma16816(a1, ah, q0.z, q0.w);
                mma16816(a1, al, q0.z, q0.w);
                mma16816(a1, ah, q2.z, q2.w);
                mma16816(a2, ah, q1.x, q1.y);
                mma16816(a2, al, q1.x, q1.y);
                mma16816(a2, ah, q3.x, q3.y);
                mma16816(a3, ah, q1.z, q1.w);
                mma16816(a3, al, q1.z, q1.w);
                mma16816(a3, ah, q3.z, q3.w);
            }
        }
    }

    // ---- Epilogue: warp-private smem transpose -> coalesced STG.128 ----
    __syncthreads();   // all warps done reading A tile
    float* scratch = (float*)smA + warp * 1024;   // 4KB per warp

#pragma unroll
    for (int mt = 0; mt < 2; mt++) {
#pragma unroll
        for (int nt = 0; nt < 4; nt++) {
#pragma unroll
            for (int j = 0; j < 4; j++) {
                int o   = nt * 8 + (lane & 3) * 2 + (j & 1);
                int pix = mt * 16 + (j >> 1) * 8 + (lane >> 2);
                scratch[o * 32 + pix] = acc[mt][nt][j] + bfc[o];
            }
        }
    }
    __syncwarp();

    const int gy = gy0 + (warp >> 1);
    float* ob = out + (size_t)b * COUT * HW + (size_t)gy * W_ + gx0 + (warp & 1) * 32;
#pragma unroll
    for (int k = 0; k < 8; k++) {
        int o  = 4 * k + (lane >> 3);
        int xl = (lane & 7) * 4;
        float4 v = *(float4*)&scratch[o * 32 + xl];
        *(float4*)(ob + (size_t)o * HW + xl) = v;
    }
}

// ---------------------------------------------------------------------------
extern "C" void kernel_launch(void* const* d_in, const int* in_sizes, int n_in,
                              void* d_out, int out_size) {
    const float* x    = (const float*)d_in[0];
    const float* cond = (const float*)d_in[1];
    const float* lpe  = (const float*)d_in[2];
    const float* w    = (const float*)d_in[3];
    const float* bias = (const float*)d_in[4];
    const float* wa_w = (const float*)d_in[5];
    const float* wa_b = (const float*)d_in[6];
    const float* ba_w = (const float*)d_in[7];
    const float* ba_b = (const float*)d_in[8];
    float* out = (float*)d_out;

    cudaFuncSetAttribute(conv_mma,
                         cudaFuncAttributeMaxDynamicSharedMemorySize, ABYTES);

    prep_kernel<<<dim3(9, B_), 128>>>(cond, lpe, wa_w, wa_b, ba_w, ba_b, bias, w);

    dim3 grid(W_ / 64, H_ / 4, B_);
    conv_mma<<<grid, NTHR, ABYTES>>>(x, out);
}